// round 2
// baseline (speedup 1.0000x reference)
#include <cuda_runtime.h>
#include <cstdint>

#define TT 4
#define HH 16

using u64 = unsigned long long;

// ---------------- helpers ----------------

__device__ __forceinline__ u64 pk2(float lo, float hi) {
    u64 r; asm("mov.b64 %0, {%1, %2};" : "=l"(r) : "f"(lo), "f"(hi)); return r;
}
__device__ __forceinline__ void up2(u64 v, float& a, float& b) {
    asm("mov.b64 {%0, %1}, %2;" : "=f"(a), "=f"(b) : "l"(v));
}
__device__ __forceinline__ u64 fma2(u64 a, u64 b, u64 c) {
    u64 d; asm("fma.rn.f32x2 %0, %1, %2, %3;" : "=l"(d) : "l"(a), "l"(b), "l"(c)); return d;
}
__device__ __forceinline__ u64 add2(u64 a, u64 b) {
    u64 d; asm("add.rn.f32x2 %0, %1, %2;" : "=l"(d) : "l"(a), "l"(b)); return d;
}
__device__ __forceinline__ float tanha(float x) {
    float y; asm("tanh.approx.f32 %0, %1;" : "=f"(y) : "f"(x)); return y;
}
__device__ __forceinline__ float sigm(float x) { return fmaf(0.5f, tanha(0.5f * x), 0.5f); }

// volatile shared loads: can't be hoisted/CSE'd across unrolled t iterations
__device__ __forceinline__ void lds128(u64& a, u64& b, unsigned addr) {
    asm volatile("ld.shared.v2.u64 {%0, %1}, [%2];" : "=l"(a), "=l"(b) : "r"(addr));
}
__device__ __forceinline__ u64 lds64(unsigned addr) {
    u64 a; asm volatile("ld.shared.u64 %0, [%1];" : "=l"(a) : "r"(addr)); return a;
}

// ---------------- shared layout (bytes) ----------------
// rz pair p (p<8: r rows 2p,2p+1 ; p>=8: z rows 16+2(p-8), +1), stride 160:
//   [  0..128) 8x float4: (whh[ga][k], whh[gb][k], whh[ga][k+1], whh[gb][k+1]), k=2*kk
//   [128..144) (wih[ga][0], wih[gb][0], wih[ga][1], wih[gb][1])
//   [144..152) (b_ih[ga]+b_hh[ga], b_ih[gb]+b_hh[gb])
// n pair p (rows 32+2p), base 2560, stride 160:
//   [  0..128) whh float4s as above
//   [128..144) wih float4
//   [144..152) (b_ih[ga], b_ih[gb])
//   [152..160) (b_hh[ga], b_hh[gb])
// 3840: w_sum[16] ; 3904: w_car[16] ; 3968: b_sum ; 3972: b_car

__global__ void __launch_bounds__(128, 3)
gru_adder_kernel(const float* __restrict__ x,
                 const float* __restrict__ w_ih,   // [48,2]
                 const float* __restrict__ w_hh,   // [48,16]
                 const float* __restrict__ b_ih,   // [48]
                 const float* __restrict__ b_hh,   // [48]
                 const float* __restrict__ w_sum,  // [16]
                 const float* __restrict__ b_sum,  // [1]
                 const float* __restrict__ w_car,  // [16]
                 const float* __restrict__ b_car,  // [1]
                 float* __restrict__ out_hidden,   // [B,4,16]
                 float* __restrict__ out_sums,     // [B,4]
                 float* __restrict__ out_carry,    // [B]
                 float* __restrict__ out_ol,       // [B,5]
                 int Bn)
{
    __shared__ float sm[1024];
    const int tid = threadIdx.x;

    // ---- fill shared ----
    for (int idx = tid; idx < 16 * 38; idx += 128) {
        int p = idx / 38, q = idx - p * 38;
        int ga = (p < 8) ? 2 * p : 16 + 2 * (p - 8);
        int gb = ga + 1;
        float v;
        if (q < 32) {
            int kk = q >> 2, r = q & 3;
            int g = (r & 1) ? gb : ga;
            v = w_hh[g * 16 + 2 * kk + (r >> 1)];
        } else if (q < 36) {
            int r = q - 32;
            v = w_ih[((r & 1) ? gb : ga) * 2 + (r >> 1)];
        } else {
            int g = (q == 36) ? ga : gb;
            v = b_ih[g] + b_hh[g];
        }
        sm[p * 40 + q] = v;
    }
    for (int idx = tid; idx < 8 * 40; idx += 128) {
        int p = idx / 40, q = idx - p * 40;
        int ga = 32 + 2 * p, gb = ga + 1;
        float v;
        if (q < 32) {
            int kk = q >> 2, r = q & 3;
            int g = (r & 1) ? gb : ga;
            v = w_hh[g * 16 + 2 * kk + (r >> 1)];
        } else if (q < 36) {
            int r = q - 32;
            v = w_ih[((r & 1) ? gb : ga) * 2 + (r >> 1)];
        } else if (q < 38) {
            v = b_ih[(q == 36) ? ga : gb];
        } else {
            v = b_hh[(q == 38) ? ga : gb];
        }
        sm[640 + p * 40 + q] = v;
    }
    if (tid < 16)        sm[960 + tid] = w_sum[tid];
    else if (tid < 32)   sm[976 + tid - 16] = w_car[tid - 16];
    else if (tid == 32)  sm[992] = b_sum[0];
    else if (tid == 33)  sm[993] = b_car[0];
    __syncthreads();

    const unsigned sbase = (unsigned)__cvta_generic_to_shared(sm);

    const int b = blockIdx.x * 128 + tid;
    if (b >= Bn) return;

    const float bs = sm[992];
    const float bc = sm[993];

    // x: 8 contiguous floats -> 2 coalesced float4 loads
    const float4* xv = reinterpret_cast<const float4*>(x + (size_t)b * 8);
    float4 xa = xv[0], xb = xv[1];
    float xs[8] = {xa.x, xa.y, xa.z, xa.w, xb.x, xb.y, xb.z, xb.w};

    u64 hd[HH];               // (h_k, h_k) dup packs
#pragma unroll
    for (int j = 0; j < HH; j++) hd[j] = 0ull;

    float sums[TT];
    float4* oh = reinterpret_cast<float4*>(out_hidden + (size_t)b * (TT * HH));

#pragma unroll
    for (int t = 0; t < TT; t++) {
        const u64 xd0 = pk2(xs[2 * t], xs[2 * t]);
        const u64 xd1 = pk2(xs[2 * t + 1], xs[2 * t + 1]);

        float r[HH];
        // ---- r gates (pairs p=0..7) ----
#pragma unroll
        for (int p = 0; p < 8; p++) {
            unsigned base = sbase + p * 160;
            u64 acc = lds64(base + 144);
            u64 xw0, xw1; lds128(xw0, xw1, base + 128);
            acc = fma2(xw0, xd0, acc);
            acc = fma2(xw1, xd1, acc);
            if (t > 0) {
                u64 acc2 = 0ull;
#pragma unroll
                for (int kk = 0; kk < 8; kk++) {
                    u64 wa, wb; lds128(wa, wb, base + kk * 16);
                    acc  = fma2(wa, hd[2 * kk], acc);
                    acc2 = fma2(wb, hd[2 * kk + 1], acc2);
                }
                acc = add2(acc, acc2);
            }
            float a0, a1; up2(acc, a0, a1);
            r[2 * p] = sigm(a0); r[2 * p + 1] = sigm(a1);
        }

        // ---- n gates (pairs p=0..7, uses r) ----
        float nn[HH];
#pragma unroll
        for (int p = 0; p < 8; p++) {
            unsigned base = sbase + 2560 + p * 160;
            u64 ia = lds64(base + 144);
            u64 xw0, xw1; lds128(xw0, xw1, base + 128);
            ia = fma2(xw0, xd0, ia);
            ia = fma2(xw1, xd1, ia);
            u64 ha = lds64(base + 152);
            if (t > 0) {
                u64 ha2 = 0ull;
#pragma unroll
                for (int kk = 0; kk < 8; kk++) {
                    u64 wa, wb; lds128(wa, wb, base + kk * 16);
                    ha  = fma2(wa, hd[2 * kk], ha);
                    ha2 = fma2(wb, hd[2 * kk + 1], ha2);
                }
                ha = add2(ha, ha2);
            }
            float i0, i1, g0, g1;
            up2(ia, i0, i1);
            up2(ha, g0, g1);
            nn[2 * p]     = tanha(fmaf(r[2 * p],     g0, i0));
            nn[2 * p + 1] = tanha(fmaf(r[2 * p + 1], g1, i1));
        }

        // ---- z gates (pairs p=8..15); must finish all dots before h update ----
        float z[HH];
#pragma unroll
        for (int p = 0; p < 8; p++) {
            unsigned base = sbase + (8 + p) * 160;
            u64 acc = lds64(base + 144);
            u64 xw0, xw1; lds128(xw0, xw1, base + 128);
            acc = fma2(xw0, xd0, acc);
            acc = fma2(xw1, xd1, acc);
            if (t > 0) {
                u64 acc2 = 0ull;
#pragma unroll
                for (int kk = 0; kk < 8; kk++) {
                    u64 wa, wb; lds128(wa, wb, base + kk * 16);
                    acc  = fma2(wa, hd[2 * kk], acc);
                    acc2 = fma2(wb, hd[2 * kk + 1], acc2);
                }
                acc = add2(acc, acc2);
            }
            float a0, a1; up2(acc, a0, a1);
            z[2 * p] = sigm(a0); z[2 * p + 1] = sigm(a1);
        }

        // ---- update h, sum logit, store hidden ----
        float s = bs;
        float hh[HH];
#pragma unroll
        for (int p = 0; p < 8; p++) {
            float o0, o1, d0, d1;
            up2(hd[2 * p], o0, d0);       // d0 == o0 (dup)
            up2(hd[2 * p + 1], o1, d1);
            float n0 = nn[2 * p], n1 = nn[2 * p + 1];
            float h0 = fmaf(z[2 * p],     o0 - n0, n0);   // (1-z)n + z h
            float h1 = fmaf(z[2 * p + 1], o1 - n1, n1);
            hd[2 * p]     = pk2(h0, h0);
            hd[2 * p + 1] = pk2(h1, h1);
            hh[2 * p] = h0; hh[2 * p + 1] = h1;
            u64 ws = lds64(sbase + 3840 + p * 8);
            float w0, w1; up2(ws, w0, w1);
            s = fmaf(h0, w0, s);
            s = fmaf(h1, w1, s);
        }
        sums[t] = s;

        oh[t * 4 + 0] = make_float4(hh[0],  hh[1],  hh[2],  hh[3]);
        oh[t * 4 + 1] = make_float4(hh[4],  hh[5],  hh[6],  hh[7]);
        oh[t * 4 + 2] = make_float4(hh[8],  hh[9],  hh[10], hh[11]);
        oh[t * 4 + 3] = make_float4(hh[12], hh[13], hh[14], hh[15]);
    }

    // ---- carry logit ----
    float c = bc;
#pragma unroll
    for (int p = 0; p < 8; p++) {
        u64 wcp = lds64(sbase + 3904 + p * 8);
        float w0, w1; up2(wcp, w0, w1);
        float h0, h1, dmy;
        up2(hd[2 * p], h0, dmy);
        up2(hd[2 * p + 1], h1, dmy);
        c = fmaf(h0, w0, c);
        c = fmaf(h1, w1, c);
    }

    reinterpret_cast<float4*>(out_sums)[b] =
        make_float4(sums[0], sums[1], sums[2], sums[3]);
    out_carry[b] = c;

    float* ol = out_ol + (size_t)b * 5;
    ol[0] = sums[0]; ol[1] = sums[1]; ol[2] = sums[2]; ol[3] = sums[3]; ol[4] = c;
}

// ---------------- launch ----------------

extern "C" void kernel_launch(void* const* d_in, const int* in_sizes, int n_in,
                              void* d_out, int out_size)
{
    const float* x     = (const float*)d_in[0];
    const float* w_ih  = (const float*)d_in[1];
    const float* w_hh  = (const float*)d_in[2];
    const float* b_ih  = (const float*)d_in[3];
    const float* b_hh  = (const float*)d_in[4];
    const float* w_sum = (const float*)d_in[5];
    const float* b_sum = (const float*)d_in[6];
    const float* w_car = (const float*)d_in[7];
    const float* b_car = (const float*)d_in[8];

    const int B = in_sizes[0] / (TT * 2);   // x is [B, T=4, I=2]

    float* out = (float*)d_out;
    float* out_hidden = out;                                  // B*64
    float* out_sums   = out_hidden + (size_t)B * TT * HH;     // B*4
    float* out_carry  = out_sums + (size_t)B * TT;            // B
    float* out_ol     = out_carry + (size_t)B;                // B*5

    const int threads = 128;
    const int blocks = (B + threads - 1) / threads;
    gru_adder_kernel<<<blocks, threads>>>(x, w_ih, w_hh, b_ih, b_hh,
                                          w_sum, b_sum, w_car, b_car,
                                          out_hidden, out_sums, out_carry,
                                          out_ol, B);
}

// round 3
// speedup vs baseline: 5.1215x; 5.1215x over previous
#include <cuda_runtime.h>
#include <cstdint>

using u64 = unsigned long long;

#define FULL 0xffffffffu

__device__ __forceinline__ u64 pk2(float lo, float hi) {
    u64 r; asm("mov.b64 %0, {%1, %2};" : "=l"(r) : "f"(lo), "f"(hi)); return r;
}
__device__ __forceinline__ void up2(u64 v, float& a, float& b) {
    asm("mov.b64 {%0, %1}, %2;" : "=f"(a), "=f"(b) : "l"(v));
}
__device__ __forceinline__ u64 fma2(u64 a, u64 b, u64 c) {
    u64 d; asm("fma.rn.f32x2 %0, %1, %2, %3;" : "=l"(d) : "l"(a), "l"(b), "l"(c)); return d;
}
__device__ __forceinline__ float tanha(float x) {
    float y; asm("tanh.approx.f32 %0, %1;" : "=f"(y) : "f"(x)); return y;
}
__device__ __forceinline__ float sigm(float x) { return fmaf(0.5f, tanha(0.5f * x), 0.5f); }

// Lane-parallel GRU: 16 lanes per batch element; lane j owns h_j and gate
// rows j (r), 16+j (z), 32+j (n). All weights in registers; h broadcast via
// shuffles; dots via fma.rn.f32x2. Grid-stride persistent loop amortizes the
// weight-load prologue. No per-thread arrays -> no spills.

__global__ void __launch_bounds__(128, 4)
gru_adder_kernel(const float* __restrict__ x,
                 const float* __restrict__ w_ih,   // [48,2]
                 const float* __restrict__ w_hh,   // [48,16]
                 const float* __restrict__ b_ih,   // [48]
                 const float* __restrict__ b_hh,   // [48]
                 const float* __restrict__ w_sum,  // [16]
                 const float* __restrict__ b_sum,  // [1]
                 const float* __restrict__ w_car,  // [16]
                 const float* __restrict__ b_car,  // [1]
                 float* __restrict__ out_hidden,   // [B,4,16]
                 float* __restrict__ out_sums,     // [B,4]
                 float* __restrict__ out_carry,    // [B]
                 float* __restrict__ out_ol,       // [B,5]
                 int Bn)
{
    const int lane = threadIdx.x & 31;
    const int warp = threadIdx.x >> 5;
    const int j    = lane & 15;          // hidden index owned by this lane
    const int g    = lane >> 4;          // which of the warp's 2 elements

    // ---- per-lane weights (registers, loaded once) ----
    const float2* whh2 = reinterpret_cast<const float2*>(w_hh);
    u64 wr[8], wz[8], wn[8];
#pragma unroll
    for (int k = 0; k < 8; k++) {
        float2 a = whh2[j * 8 + k];         wr[k] = pk2(a.x, a.y);
        float2 b = whh2[(16 + j) * 8 + k];  wz[k] = pk2(b.x, b.y);
        float2 c = whh2[(32 + j) * 8 + k];  wn[k] = pk2(c.x, c.y);
    }
    const float2 wxr = reinterpret_cast<const float2*>(w_ih)[j];
    const float2 wxz = reinterpret_cast<const float2*>(w_ih)[16 + j];
    const float2 wxn = reinterpret_cast<const float2*>(w_ih)[32 + j];
    const float br  = b_ih[j]      + b_hh[j];
    const float bz  = b_ih[16 + j] + b_hh[16 + j];
    const float bni = b_ih[32 + j];
    const float bnh = b_hh[32 + j];
    const float wsj = w_sum[j];
    const float wcj = w_car[j];
    const float bs  = b_sum[0];
    const float bc  = b_car[0];

    const int stride = gridDim.x * 8;    // elements handled per grid pass

    for (int eb = blockIdx.x * 8 + warp * 2; eb < Bn; eb += stride) {
        const int e = eb + g;
        // 16 lanes load both elements' x (8 floats each), coalesced 64B
        const float xval = x[(size_t)eb * 8 + (lane & 15)];

        float h = 0.0f;
        float s0, s1, s2, s3;
        float* ohid = out_hidden + (size_t)e * 64;

#pragma unroll
        for (int t = 0; t < 4; t++) {
            const int xsrc = (g << 3) + 2 * t;
            const float xt0 = __shfl_sync(FULL, xval, xsrc, 16);
            const float xt1 = __shfl_sync(FULL, xval, xsrc + 1, 16);

            float rpre = fmaf(xt1, wxr.y, fmaf(xt0, wxr.x, br));
            float zpre = fmaf(xt1, wxz.y, fmaf(xt0, wxz.x, bz));
            float inx  = fmaf(xt1, wxn.y, fmaf(xt0, wxn.x, bni));
            float hn   = bnh;

            if (t > 0) {   // h0 == 0: skip recurrent dot at t=0
                u64 ar = 0ull, az = 0ull, an = 0ull;
#pragma unroll
                for (int k = 0; k < 8; k++) {
                    float h0 = __shfl_sync(FULL, h, 2 * k, 16);
                    float h1 = __shfl_sync(FULL, h, 2 * k + 1, 16);
                    u64 hp = pk2(h0, h1);
                    ar = fma2(wr[k], hp, ar);
                    az = fma2(wz[k], hp, az);
                    an = fma2(wn[k], hp, an);
                }
                float a0, a1;
                up2(ar, a0, a1); rpre += a0 + a1;
                up2(az, a0, a1); zpre += a0 + a1;
                up2(an, a0, a1); hn   += a0 + a1;
            }

            const float r = sigm(rpre);
            const float z = sigm(zpre);
            const float n = tanha(fmaf(r, hn, inx));
            h = fmaf(z, h - n, n);          // (1-z)n + z h

            // sum logit: reduce h*w_sum over the 16-lane group
            float s = h * wsj;
#pragma unroll
            for (int o = 8; o > 0; o >>= 1)
                s += __shfl_xor_sync(FULL, s, o, 16);
            s += bs;
            if      (t == 0) s0 = s;
            else if (t == 1) s1 = s;
            else if (t == 2) s2 = s;
            else             s3 = s;

            ohid[t * 16 + j] = h;           // warp: 2 contiguous 64B runs
        }

        // carry logit
        float cp = h * wcj;
#pragma unroll
        for (int o = 8; o > 0; o >>= 1)
            cp += __shfl_xor_sync(FULL, cp, o, 16);
        const float c = cp + bc;

        if (j == 0) out_carry[e] = c;
        if (j < 4) {
            const float sv = (j == 0) ? s0 : ((j == 1) ? s1 : ((j == 2) ? s2 : s3));
            out_sums[(size_t)e * 4 + j] = sv;
            out_ol[(size_t)e * 5 + j]   = sv;
        }
        if (j == 4) out_ol[(size_t)e * 5 + 4] = c;
    }
}

// ---------------- launch ----------------

extern "C" void kernel_launch(void* const* d_in, const int* in_sizes, int n_in,
                              void* d_out, int out_size)
{
    const float* x     = (const float*)d_in[0];
    const float* w_ih  = (const float*)d_in[1];
    const float* w_hh  = (const float*)d_in[2];
    const float* b_ih  = (const float*)d_in[3];
    const float* b_hh  = (const float*)d_in[4];
    const float* w_sum = (const float*)d_in[5];
    const float* b_sum = (const float*)d_in[6];
    const float* w_car = (const float*)d_in[7];
    const float* b_car = (const float*)d_in[8];

    const int B = in_sizes[0] / 8;   // x is [B, 4, 2]

    float* out = (float*)d_out;
    float* out_hidden = out;                              // B*64
    float* out_sums   = out_hidden + (size_t)B * 64;      // B*4
    float* out_carry  = out_sums + (size_t)B * 4;         // B
    float* out_ol     = out_carry + (size_t)B;            // B*5

    const int threads = 128;
    int blocks = 1480;                 // persistent grid-stride (~10 blocks/SM)
    int maxb = (B + 7) / 8;
    if (blocks > maxb) blocks = maxb;

    gru_adder_kernel<<<blocks, threads>>>(x, w_ih, w_hh, b_ih, b_hh,
                                          w_sum, b_sum, w_car, b_car,
                                          out_hidden, out_sums, out_carry,
                                          out_ol, B);
}

// round 4
// speedup vs baseline: 9.5087x; 1.8566x over previous
#include <cuda_runtime.h>
#include <cstdint>

using u32 = unsigned int;
#define FULL 0xffffffffu

__device__ __forceinline__ float tanha(float x) {
    float y; asm("tanh.approx.f32 %0, %1;" : "=f"(y) : "f"(x)); return y;
}
__device__ __forceinline__ float sigm(float x) { return fmaf(0.5f, tanha(0.5f * x), 0.5f); }
__device__ __forceinline__ u32 t32(float v) {
    u32 r; asm("cvt.rna.tf32.f32 %0, %1;" : "=r"(r) : "f"(v)); return r;
}

// d = a(16x8 tf32) @ b(8x8 tf32) + c
__device__ __forceinline__ void mma8(float d[4], const u32 a[4], const u32 b[2],
                                     const float c[4]) {
    asm("mma.sync.aligned.m16n8k8.row.col.f32.tf32.tf32.f32 "
        "{%0,%1,%2,%3}, {%4,%5,%6,%7}, {%8,%9}, {%10,%11,%12,%13};"
        : "=f"(d[0]), "=f"(d[1]), "=f"(d[2]), "=f"(d[3])
        : "r"(a[0]), "r"(a[1]), "r"(a[2]), "r"(a[3]),
          "r"(b[0]), "r"(b[1]),
          "f"(c[0]), "f"(c[1]), "f"(c[2]), "f"(c[3]));
}

// Output-column permutation: accumulator position p holds h component pi(p),
// chosen so each lane's accum slots are exactly its next-step A-frag slots.
__device__ __forceinline__ int pi_map(int p) {
    return (p < 8) ? ((p >> 1) | ((p & 1) << 2))
                   : (8 | (((p - 8) >> 1)) | ((p & 1) << 2));
}

// B element value: col = permuted output col (0..63), k = 0..23
// groups: col/16 = 0:r  1:z  2:h_n (whh only)  3:i_n (wih only)
__device__ __forceinline__ float bval(const float* w_ih, const float* w_hh,
                                      int col, int k) {
    int grp = col >> 4;
    int g = pi_map(col & 15);
    if (grp == 0 || grp == 1) {
        g += grp * 16;
        if (k < 16) return w_hh[g * 16 + k];
        if (k < 18) return w_ih[g * 2 + (k - 16)];
        return 0.0f;
    }
    g += 32;
    if (grp == 2) return (k < 16) ? w_hh[g * 16 + k] : 0.0f;
    if (k == 16) return w_ih[g * 2];
    if (k == 17) return w_ih[g * 2 + 1];
    return 0.0f;
}

__global__ void __launch_bounds__(128)
gru_adder_kernel(const float* __restrict__ x,
                 const float* __restrict__ w_ih,   // [48,2]
                 const float* __restrict__ w_hh,   // [48,16]
                 const float* __restrict__ b_ih,   // [48]
                 const float* __restrict__ b_hh,   // [48]
                 const float* __restrict__ w_sum,  // [16]
                 const float* __restrict__ b_sum,  // [1]
                 const float* __restrict__ w_car,  // [16]
                 const float* __restrict__ b_car,  // [1]
                 float* __restrict__ out_hidden,   // [B,4,16]
                 float* __restrict__ out_sums,     // [B,4]
                 float* __restrict__ out_carry,    // [B]
                 float* __restrict__ out_ol,       // [B,5]
                 int Bn)
{
    const int warp = threadIdx.x >> 5;
    const int l = threadIdx.x & 31;
    const int q = l & 3;      // lane quad position
    const int a = l >> 2;     // row group: rows a and a+8

    // ---------- per-lane B fragments (hi/lo tf32 split), built once ----------
    // rz tiles 0..3 (cols 0..31): k-chunks 0,1 (h) + 2 (x)
    u32 Bh[4][3][2], Bl[4][3][2];
#pragma unroll
    for (int nt = 0; nt < 4; nt++) {
#pragma unroll
        for (int kc = 0; kc < 3; kc++) {
            int col = nt * 8 + a;
            float v0 = bval(w_ih, w_hh, col, kc * 8 + q);
            float v1 = bval(w_ih, w_hh, col, kc * 8 + q + 4);
            Bh[nt][kc][0] = t32(v0);
            Bl[nt][kc][0] = t32(v0 - __uint_as_float(Bh[nt][kc][0]));
            Bh[nt][kc][1] = t32(v1);
            Bl[nt][kc][1] = t32(v1 - __uint_as_float(Bh[nt][kc][1]));
        }
    }
    // h_n tiles 4,5: k-chunks 0,1 only
    u32 Hh[2][2][2], Hl[2][2][2];
#pragma unroll
    for (int ti = 0; ti < 2; ti++) {
#pragma unroll
        for (int kc = 0; kc < 2; kc++) {
            int col = (4 + ti) * 8 + a;
            float v0 = bval(w_ih, w_hh, col, kc * 8 + q);
            float v1 = bval(w_ih, w_hh, col, kc * 8 + q + 4);
            Hh[ti][kc][0] = t32(v0);
            Hl[ti][kc][0] = t32(v0 - __uint_as_float(Hh[ti][kc][0]));
            Hh[ti][kc][1] = t32(v1);
            Hl[ti][kc][1] = t32(v1 - __uint_as_float(Hh[ti][kc][1]));
        }
    }
    // i_n tiles 6,7: k-chunk 2 only
    u32 Ih[2][2], Il[2][2];
#pragma unroll
    for (int ti = 0; ti < 2; ti++) {
        int col = (6 + ti) * 8 + a;
        float v0 = bval(w_ih, w_hh, col, 16 + q);
        float v1 = bval(w_ih, w_hh, col, 20 + q);
        Ih[ti][0] = t32(v0);
        Il[ti][0] = t32(v0 - __uint_as_float(Ih[ti][0]));
        Ih[ti][1] = t32(v1);
        Il[ti][1] = t32(v1 - __uint_as_float(Ih[ti][1]));
    }

    // ---------- per-lane bias c-init (cols 2q, 2q+1 of each tile) ----------
    float cb[8][2];
#pragma unroll
    for (int nt = 0; nt < 8; nt++) {
#pragma unroll
        for (int bb = 0; bb < 2; bb++) {
            int col = nt * 8 + 2 * q + bb;
            int grp = col >> 4;
            int g = pi_map(col & 15);
            float v;
            if (grp == 0)      v = b_ih[g] + b_hh[g];
            else if (grp == 1) v = b_ih[16 + g] + b_hh[16 + g];
            else if (grp == 2) v = b_hh[32 + g];
            else               v = b_ih[32 + g];
            cb[nt][bb] = v;
        }
    }

    // sum / carry weights at this lane's h components {q, q+4, 8+q, 12+q}
    float ws[4], wc[4];
#pragma unroll
    for (int m = 0; m < 4; m++) {
        int j = q + ((m & 1) << 2) + ((m >> 1) << 3);
        ws[m] = w_sum[j];
        wc[m] = w_car[j];
    }
    const float bs = b_sum[0];
    const float bc = b_car[0];

    // ---------- persistent loop over 16-row tiles ----------
    const int ntiles = Bn >> 4;
    const int nwarp = blockDim.x >> 5;

    for (int tile = blockIdx.x * nwarp + warp; tile < ntiles;
         tile += gridDim.x * nwarp) {
        const int e0 = tile * 16;
        const int er0 = e0 + a, er1 = e0 + a + 8;

        // x values: lane q<2 holds x[row][2t+q] for t=0..3, rows er0/er1
        u32 xh0[4], xl0[4], xh1[4], xl1[4];
#pragma unroll
        for (int t = 0; t < 4; t++) {
            float v0 = 0.0f, v1 = 0.0f;
            if (q < 2) {
                v0 = x[(size_t)er0 * 8 + 2 * t + q];
                v1 = x[(size_t)er1 * 8 + 2 * t + q];
            }
            xh0[t] = t32(v0); xl0[t] = t32(v0 - __uint_as_float(xh0[t]));
            xh1[t] = t32(v1); xl1[t] = t32(v1 - __uint_as_float(xh1[t]));
        }

        // h state: hr0[m]/hr1[m] = h[row][component q+4*(m&1)+8*(m>>1)]
        float hr0[4] = {0.f, 0.f, 0.f, 0.f};
        float hr1[4] = {0.f, 0.f, 0.f, 0.f};

        float* oh0 = out_hidden + (size_t)er0 * 64;
        float* oh1 = out_hidden + (size_t)er1 * 64;

#pragma unroll
        for (int t = 0; t < 4; t++) {
            float acc[8][4];
#pragma unroll
            for (int nt = 0; nt < 8; nt++) {
                acc[nt][0] = cb[nt][0]; acc[nt][1] = cb[nt][1];
                acc[nt][2] = cb[nt][0]; acc[nt][3] = cb[nt][1];
            }

            if (t > 0) {
                // A-frags for h chunks straight from accum-layout h (no shuffles)
                u32 ahh[2][4], ahl[2][4];
#pragma unroll
                for (int kc = 0; kc < 2; kc++) {
                    ahh[kc][0] = t32(hr0[2 * kc]);
                    ahh[kc][1] = t32(hr1[2 * kc]);
                    ahh[kc][2] = t32(hr0[2 * kc + 1]);
                    ahh[kc][3] = t32(hr1[2 * kc + 1]);
                    ahl[kc][0] = t32(hr0[2 * kc]     - __uint_as_float(ahh[kc][0]));
                    ahl[kc][1] = t32(hr1[2 * kc]     - __uint_as_float(ahh[kc][1]));
                    ahl[kc][2] = t32(hr0[2 * kc + 1] - __uint_as_float(ahh[kc][2]));
                    ahl[kc][3] = t32(hr1[2 * kc + 1] - __uint_as_float(ahh[kc][3]));
                }
#pragma unroll
                for (int nt = 0; nt < 4; nt++) {
#pragma unroll
                    for (int kc = 0; kc < 2; kc++) {
                        mma8(acc[nt], ahh[kc], Bh[nt][kc], acc[nt]);
                        mma8(acc[nt], ahh[kc], Bl[nt][kc], acc[nt]);
                        mma8(acc[nt], ahl[kc], Bh[nt][kc], acc[nt]);
                    }
                }
#pragma unroll
                for (int ti = 0; ti < 2; ti++) {
#pragma unroll
                    for (int kc = 0; kc < 2; kc++) {
                        mma8(acc[4 + ti], ahh[kc], Hh[ti][kc], acc[4 + ti]);
                        mma8(acc[4 + ti], ahh[kc], Hl[ti][kc], acc[4 + ti]);
                        mma8(acc[4 + ti], ahl[kc], Hh[ti][kc], acc[4 + ti]);
                    }
                }
            }

            // x chunk (k-chunk 2)
            {
                u32 axh[4] = {xh0[t], xh1[t], 0u, 0u};
                u32 axl[4] = {xl0[t], xl1[t], 0u, 0u};
#pragma unroll
                for (int nt = 0; nt < 4; nt++) {
                    mma8(acc[nt], axh, Bh[nt][2], acc[nt]);
                    mma8(acc[nt], axh, Bl[nt][2], acc[nt]);
                    mma8(acc[nt], axl, Bh[nt][2], acc[nt]);
                }
#pragma unroll
                for (int ti = 0; ti < 2; ti++) {
                    mma8(acc[6 + ti], axh, Ih[ti], acc[6 + ti]);
                    mma8(acc[6 + ti], axh, Il[ti], acc[6 + ti]);
                    mma8(acc[6 + ti], axl, Ih[ti], acc[6 + ti]);
                }
            }

            // ---------- epilogue: activations + h update ----------
#pragma unroll
            for (int m = 0; m < 4; m++) {
                const int toff = m >> 1, pr = m & 1;
                // row a
                {
                    float r = sigm(acc[0 + toff][pr]);
                    float z = sigm(acc[2 + toff][pr]);
                    float n = tanha(fmaf(r, acc[4 + toff][pr], acc[6 + toff][pr]));
                    hr0[m] = fmaf(z, hr0[m] - n, n);
                }
                // row a+8
                {
                    float r = sigm(acc[0 + toff][2 + pr]);
                    float z = sigm(acc[2 + toff][2 + pr]);
                    float n = tanha(fmaf(r, acc[4 + toff][2 + pr], acc[6 + toff][2 + pr]));
                    hr1[m] = fmaf(z, hr1[m] - n, n);
                }
                const int col = q + ((m & 1) << 2) + ((m >> 1) << 3);
                oh0[t * 16 + col] = hr0[m];
                oh1[t * 16 + col] = hr1[m];
            }

            // ---------- sum logits ----------
            float s0 = hr0[0] * ws[0] + hr0[1] * ws[1] + hr0[2] * ws[2] + hr0[3] * ws[3];
            float s1 = hr1[0] * ws[0] + hr1[1] * ws[1] + hr1[2] * ws[2] + hr1[3] * ws[3];
            s0 += __shfl_xor_sync(FULL, s0, 1);
            s0 += __shfl_xor_sync(FULL, s0, 2);
            s1 += __shfl_xor_sync(FULL, s1, 1);
            s1 += __shfl_xor_sync(FULL, s1, 2);
            if (q == 0) {
                out_sums[(size_t)er0 * 4 + t] = s0 + bs;
                out_sums[(size_t)er1 * 4 + t] = s1 + bs;
                out_ol[(size_t)er0 * 5 + t] = s0 + bs;
                out_ol[(size_t)er1 * 5 + t] = s1 + bs;
            }
        }

        // ---------- carry logit ----------
        float c0 = hr0[0] * wc[0] + hr0[1] * wc[1] + hr0[2] * wc[2] + hr0[3] * wc[3];
        float c1 = hr1[0] * wc[0] + hr1[1] * wc[1] + hr1[2] * wc[2] + hr1[3] * wc[3];
        c0 += __shfl_xor_sync(FULL, c0, 1);
        c0 += __shfl_xor_sync(FULL, c0, 2);
        c1 += __shfl_xor_sync(FULL, c1, 1);
        c1 += __shfl_xor_sync(FULL, c1, 2);
        if (q == 0) {
            out_carry[er0] = c0 + bc;
            out_carry[er1] = c1 + bc;
            out_ol[(size_t)er0 * 5 + 4] = c0 + bc;
            out_ol[(size_t)er1 * 5 + 4] = c1 + bc;
        }
    }
}

// ---------------- launch ----------------

extern "C" void kernel_launch(void* const* d_in, const int* in_sizes, int n_in,
                              void* d_out, int out_size)
{
    const float* x     = (const float*)d_in[0];
    const float* w_ih  = (const float*)d_in[1];
    const float* w_hh  = (const float*)d_in[2];
    const float* b_ih  = (const float*)d_in[3];
    const float* b_hh  = (const float*)d_in[4];
    const float* w_sum = (const float*)d_in[5];
    const float* b_sum = (const float*)d_in[6];
    const float* w_car = (const float*)d_in[7];
    const float* b_car = (const float*)d_in[8];

    const int B = in_sizes[0] / 8;   // x is [B, 4, 2]

    float* out = (float*)d_out;
    float* out_hidden = out;                              // B*64
    float* out_sums   = out_hidden + (size_t)B * 64;      // B*4
    float* out_carry  = out_sums + (size_t)B * 4;         // B
    float* out_ol     = out_carry + (size_t)B;            // B*5

    const int threads = 128;                // 4 warps/block
    int blocks = 296;                       // persistent, ~2 blocks/SM
    int maxb = (B / 16 + 3) / 4;
    if (blocks > maxb) blocks = maxb;

    gru_adder_kernel<<<blocks, threads>>>(x, w_ih, w_hh, b_ih, b_hh,
                                          w_sum, b_sum, w_car, b_car,
                                          out_hidden, out_sums, out_carry,
                                          out_ol, B);
}

// round 5
// speedup vs baseline: 10.9316x; 1.1496x over previous
#include <cuda_runtime.h>
#include <cstdint>

using u32 = unsigned int;
#define FULL 0xffffffffu

__device__ __forceinline__ float tanha(float x) {
    float y; asm("tanh.approx.f32 %0, %1;" : "=f"(y) : "f"(x)); return y;
}
__device__ __forceinline__ float sigm(float x) { return fmaf(0.5f, tanha(0.5f * x), 0.5f); }
__device__ __forceinline__ u32 t32(float v) {
    u32 r; asm("cvt.rna.tf32.f32 %0, %1;" : "=r"(r) : "f"(v)); return r;
}

// d = a(16x8 tf32) @ b(8x8 tf32) + c
__device__ __forceinline__ void mma8(float d[4], const u32 a[4], const u32 b[2],
                                     const float c[4]) {
    asm("mma.sync.aligned.m16n8k8.row.col.f32.tf32.tf32.f32 "
        "{%0,%1,%2,%3}, {%4,%5,%6,%7}, {%8,%9}, {%10,%11,%12,%13};"
        : "=f"(d[0]), "=f"(d[1]), "=f"(d[2]), "=f"(d[3])
        : "r"(a[0]), "r"(a[1]), "r"(a[2]), "r"(a[3]),
          "r"(b[0]), "r"(b[1]),
          "f"(c[0]), "f"(c[1]), "f"(c[2]), "f"(c[3]));
}

// Accumulator position p holds h component pi(p): lane accum slots == next-step
// A-frag slots, so the recurrence needs no shuffles.
__device__ __forceinline__ int pi_map(int p) {
    return (p < 8) ? ((p >> 1) | ((p & 1) << 2))
                   : (8 | (((p - 8) >> 1)) | ((p & 1) << 2));
}

// B (h-part only) element: col = permuted output col (0..47), k = 0..15
// groups: col/16 = 0:r  1:z  2:h_n     (all read w_hh)
__device__ __forceinline__ float bval_h(const float* w_hh, int col, int k) {
    int grp = col >> 4;
    int g = pi_map(col & 15) + grp * 16;
    return w_hh[g * 16 + k];
}

__global__ void __launch_bounds__(160, 2)
gru_adder_kernel(const float* __restrict__ x,
                 const float* __restrict__ w_ih,   // [48,2]
                 const float* __restrict__ w_hh,   // [48,16]
                 const float* __restrict__ b_ih,   // [48]
                 const float* __restrict__ b_hh,   // [48]
                 const float* __restrict__ w_sum,  // [16]
                 const float* __restrict__ b_sum,  // [1]
                 const float* __restrict__ w_car,  // [16]
                 const float* __restrict__ b_car,  // [1]
                 float* __restrict__ out_hidden,   // [B,4,16]
                 float* __restrict__ out_sums,     // [B,4]
                 float* __restrict__ out_carry,    // [B]
                 float* __restrict__ out_ol,       // [B,5]
                 int Bn)
{
    const int warp = threadIdx.x >> 5;
    const int l = threadIdx.x & 31;
    const int q = l & 3;      // lane quad position
    const int a = l >> 2;     // row group: rows a and a+8

    // ---------- per-lane B fragments (hi/lo tf32 split), h-chunks only ----------
    // tiles 0,1: r ; tiles 2,3: z
    u32 Bh[4][2][2], Bl[4][2][2];
#pragma unroll
    for (int nt = 0; nt < 4; nt++) {
#pragma unroll
        for (int kc = 0; kc < 2; kc++) {
            int col = nt * 8 + a;
            float v0 = bval_h(w_hh, col, kc * 8 + q);
            float v1 = bval_h(w_hh, col, kc * 8 + q + 4);
            Bh[nt][kc][0] = t32(v0);
            Bl[nt][kc][0] = t32(v0 - __uint_as_float(Bh[nt][kc][0]));
            Bh[nt][kc][1] = t32(v1);
            Bl[nt][kc][1] = t32(v1 - __uint_as_float(Bh[nt][kc][1]));
        }
    }
    // h_n tiles 4,5
    u32 Hh[2][2][2], Hl[2][2][2];
#pragma unroll
    for (int ti = 0; ti < 2; ti++) {
#pragma unroll
        for (int kc = 0; kc < 2; kc++) {
            int col = 32 + ti * 8 + a;
            float v0 = bval_h(w_hh, col, kc * 8 + q);
            float v1 = bval_h(w_hh, col, kc * 8 + q + 4);
            Hh[ti][kc][0] = t32(v0);
            Hl[ti][kc][0] = t32(v0 - __uint_as_float(Hh[ti][kc][0]));
            Hh[ti][kc][1] = t32(v1);
            Hl[ti][kc][1] = t32(v1 - __uint_as_float(Hh[ti][kc][1]));
        }
    }

    // ---------- per-lane x weights (scalar path, exact fp32) ----------
    // wx[0..3]: rz tiles 0..3 ; wx[4,5]: i_n tiles 6,7. Index [pr] = col 2q+pr.
    float wx0[6][2], wx1[6][2];
#pragma unroll
    for (int nt = 0; nt < 4; nt++) {
#pragma unroll
        for (int pr = 0; pr < 2; pr++) {
            int col = nt * 8 + 2 * q + pr;
            int g = pi_map(col & 15) + (col >> 4) * 16;
            wx0[nt][pr] = w_ih[g * 2];
            wx1[nt][pr] = w_ih[g * 2 + 1];
        }
    }
#pragma unroll
    for (int ti = 0; ti < 2; ti++) {
#pragma unroll
        for (int pr = 0; pr < 2; pr++) {
            int col = (6 + ti) * 8 + 2 * q + pr;   // col&15 == (ti?8:0)+2q+pr
            int g = pi_map(col & 15) + 32;
            wx0[4 + ti][pr] = w_ih[g * 2];
            wx1[4 + ti][pr] = w_ih[g * 2 + 1];
        }
    }

    // ---------- per-lane bias init ----------
    // cb[0..3]: rz (b_ih+b_hh) ; cb[4,5]: h_n (b_hh) ; cb[6,7]: i_n (b_ih)
    float cb[8][2];
#pragma unroll
    for (int nt = 0; nt < 8; nt++) {
#pragma unroll
        for (int pr = 0; pr < 2; pr++) {
            int col = nt * 8 + 2 * q + pr;
            int grp = col >> 4;
            int g = pi_map(col & 15);
            float v;
            if (grp == 0)      v = b_ih[g] + b_hh[g];
            else if (grp == 1) v = b_ih[16 + g] + b_hh[16 + g];
            else if (grp == 2) v = b_hh[32 + g];
            else               v = b_ih[32 + g];
            cb[nt][pr] = v;
        }
    }

    // sum / carry weights at this lane's h components {q, q+4, 8+q, 12+q}
    float ws[4], wc[4];
#pragma unroll
    for (int m = 0; m < 4; m++) {
        int j = q + ((m & 1) << 2) + ((m >> 1) << 3);
        ws[m] = w_sum[j];
        wc[m] = w_car[j];
    }
    const float bs = b_sum[0];
    const float bc = b_car[0];

    // ---------- persistent loop over 16-row tiles ----------
    const int ntiles = Bn >> 4;
    const int nwarp = blockDim.x >> 5;

    for (int tile = blockIdx.x * nwarp + warp; tile < ntiles;
         tile += gridDim.x * nwarp) {
        const int e0 = tile * 16;
        const int er0 = e0 + a, er1 = e0 + a + 8;

        // this lane's two rows of x (8 floats each)
        const float4* xv0 = reinterpret_cast<const float4*>(x + (size_t)er0 * 8);
        const float4* xv1 = reinterpret_cast<const float4*>(x + (size_t)er1 * 8);
        float4 A0 = xv0[0], A1 = xv0[1], C0 = xv1[0], C1 = xv1[1];
        float xs0[8] = {A0.x, A0.y, A0.z, A0.w, A1.x, A1.y, A1.z, A1.w};
        float xs1[8] = {C0.x, C0.y, C0.z, C0.w, C1.x, C1.y, C1.z, C1.w};

        // h state: hr0[m]/hr1[m] = h[row][component q+4*(m&1)+8*(m>>1)]
        float hr0[4] = {0.f, 0.f, 0.f, 0.f};
        float hr1[4] = {0.f, 0.f, 0.f, 0.f};

        float* oh0 = out_hidden + (size_t)er0 * 64;
        float* oh1 = out_hidden + (size_t)er1 * 64;

#pragma unroll
        for (int t = 0; t < 4; t++) {
            const float x00 = xs0[2 * t], x01 = xs0[2 * t + 1];
            const float x10 = xs1[2 * t], x11 = xs1[2 * t + 1];

            // acc init: biases + exact scalar x contribution
            float acc[6][4];
#pragma unroll
            for (int nt = 0; nt < 4; nt++) {
#pragma unroll
                for (int pr = 0; pr < 2; pr++) {
                    acc[nt][pr]     = fmaf(x01, wx1[nt][pr], fmaf(x00, wx0[nt][pr], cb[nt][pr]));
                    acc[nt][2 + pr] = fmaf(x11, wx1[nt][pr], fmaf(x10, wx0[nt][pr], cb[nt][pr]));
                }
            }
#pragma unroll
            for (int ti = 0; ti < 2; ti++) {
#pragma unroll
                for (int pr = 0; pr < 2; pr++) {
                    acc[4 + ti][pr]     = cb[4 + ti][pr];
                    acc[4 + ti][2 + pr] = cb[4 + ti][pr];
                }
            }
            // i_n (pure scalar, no h dependency)
            float in0[4], in1[4];
#pragma unroll
            for (int ti = 0; ti < 2; ti++) {
#pragma unroll
                for (int pr = 0; pr < 2; pr++) {
                    in0[ti * 2 + pr] = fmaf(x01, wx1[4 + ti][pr], fmaf(x00, wx0[4 + ti][pr], cb[6 + ti][pr]));
                    in1[ti * 2 + pr] = fmaf(x11, wx1[4 + ti][pr], fmaf(x10, wx0[4 + ti][pr], cb[6 + ti][pr]));
                }
            }

            if (t > 0) {
                // A-frags straight from accum-layout h (no shuffles)
                u32 ahh[2][4], ahl[2][4];
#pragma unroll
                for (int kc = 0; kc < 2; kc++) {
                    ahh[kc][0] = t32(hr0[2 * kc]);
                    ahh[kc][1] = t32(hr1[2 * kc]);
                    ahh[kc][2] = t32(hr0[2 * kc + 1]);
                    ahh[kc][3] = t32(hr1[2 * kc + 1]);
                    ahl[kc][0] = t32(hr0[2 * kc]     - __uint_as_float(ahh[kc][0]));
                    ahl[kc][1] = t32(hr1[2 * kc]     - __uint_as_float(ahh[kc][1]));
                    ahl[kc][2] = t32(hr0[2 * kc + 1] - __uint_as_float(ahh[kc][2]));
                    ahl[kc][3] = t32(hr1[2 * kc + 1] - __uint_as_float(ahh[kc][3]));
                }
#pragma unroll
                for (int nt = 0; nt < 4; nt++) {
#pragma unroll
                    for (int kc = 0; kc < 2; kc++) {
                        mma8(acc[nt], ahh[kc], Bh[nt][kc], acc[nt]);
                        mma8(acc[nt], ahh[kc], Bl[nt][kc], acc[nt]);
                        mma8(acc[nt], ahl[kc], Bh[nt][kc], acc[nt]);
                    }
                }
#pragma unroll
                for (int ti = 0; ti < 2; ti++) {
#pragma unroll
                    for (int kc = 0; kc < 2; kc++) {
                        mma8(acc[4 + ti], ahh[kc], Hh[ti][kc], acc[4 + ti]);
                        mma8(acc[4 + ti], ahh[kc], Hl[ti][kc], acc[4 + ti]);
                        mma8(acc[4 + ti], ahl[kc], Hh[ti][kc], acc[4 + ti]);
                    }
                }
            }

            // ---------- epilogue: activations + h update ----------
#pragma unroll
            for (int m = 0; m < 4; m++) {
                const int toff = m >> 1, pr = m & 1;
                {
                    float r = sigm(acc[toff][pr]);
                    float z = sigm(acc[2 + toff][pr]);
                    float n = tanha(fmaf(r, acc[4 + toff][pr], in0[toff * 2 + pr]));
                    hr0[m] = fmaf(z, hr0[m] - n, n);
                }
                {
                    float r = sigm(acc[toff][2 + pr]);
                    float z = sigm(acc[2 + toff][2 + pr]);
                    float n = tanha(fmaf(r, acc[4 + toff][2 + pr], in1[toff * 2 + pr]));
                    hr1[m] = fmaf(z, hr1[m] - n, n);
                }
                const int col = q + ((m & 1) << 2) + ((m >> 1) << 3);
                oh0[t * 16 + col] = hr0[m];
                oh1[t * 16 + col] = hr1[m];
            }

            // ---------- sum logits ----------
            float s0 = hr0[0] * ws[0] + hr0[1] * ws[1] + hr0[2] * ws[2] + hr0[3] * ws[3];
            float s1 = hr1[0] * ws[0] + hr1[1] * ws[1] + hr1[2] * ws[2] + hr1[3] * ws[3];
            s0 += __shfl_xor_sync(FULL, s0, 1);
            s0 += __shfl_xor_sync(FULL, s0, 2);
            s1 += __shfl_xor_sync(FULL, s1, 1);
            s1 += __shfl_xor_sync(FULL, s1, 2);
            if (q == 0) {
                out_sums[(size_t)er0 * 4 + t] = s0 + bs;
                out_sums[(size_t)er1 * 4 + t] = s1 + bs;
                out_ol[(size_t)er0 * 5 + t] = s0 + bs;
                out_ol[(size_t)er1 * 5 + t] = s1 + bs;
            }
        }

        // ---------- carry logit ----------
        float c0 = hr0[0] * wc[0] + hr0[1] * wc[1] + hr0[2] * wc[2] + hr0[3] * wc[3];
        float c1 = hr1[0] * wc[0] + hr1[1] * wc[1] + hr1[2] * wc[2] + hr1[3] * wc[3];
        c0 += __shfl_xor_sync(FULL, c0, 1);
        c0 += __shfl_xor_sync(FULL, c0, 2);
        c1 += __shfl_xor_sync(FULL, c1, 1);
        c1 += __shfl_xor_sync(FULL, c1, 2);
        if (q == 0) {
            out_carry[er0] = c0 + bc;
            out_carry[er1] = c1 + bc;
            out_ol[(size_t)er0 * 5 + 4] = c0 + bc;
            out_ol[(size_t)er1 * 5 + 4] = c1 + bc;
        }
    }
}

// ---------------- launch ----------------

extern "C" void kernel_launch(void* const* d_in, const int* in_sizes, int n_in,
                              void* d_out, int out_size)
{
    const float* x     = (const float*)d_in[0];
    const float* w_ih  = (const float*)d_in[1];
    const float* w_hh  = (const float*)d_in[2];
    const float* b_ih  = (const float*)d_in[3];
    const float* b_hh  = (const float*)d_in[4];
    const float* w_sum = (const float*)d_in[5];
    const float* b_sum = (const float*)d_in[6];
    const float* w_car = (const float*)d_in[7];
    const float* b_car = (const float*)d_in[8];

    const int B = in_sizes[0] / 8;   // x is [B, 4, 2]

    float* out = (float*)d_out;
    float* out_hidden = out;                              // B*64
    float* out_sums   = out_hidden + (size_t)B * 64;      // B*4
    float* out_carry  = out_sums + (size_t)B * 4;         // B
    float* out_ol     = out_carry + (size_t)B;            // B*5

    const int threads = 160;                // 5 warps/block, 2 blocks/SM
    int blocks = 296;
    int maxb = (B / 16 + 4) / 5;
    if (blocks > maxb) blocks = maxb;
    if (blocks < 1) blocks = 1;

    gru_adder_kernel<<<blocks, threads>>>(x, w_ih, w_hh, b_ih, b_hh,
                                          w_sum, b_sum, w_car, b_car,
                                          out_hidden, out_sums, out_carry,
                                          out_ol, B);
}

// round 6
// speedup vs baseline: 13.8387x; 1.2659x over previous
#include <cuda_runtime.h>
#include <cstdint>

using u32 = unsigned int;
#define FULL 0xffffffffu

__device__ __forceinline__ float tanha(float x) {
    float y; asm("tanh.approx.f32 %0, %1;" : "=f"(y) : "f"(x)); return y;
}
__device__ __forceinline__ float sigm(float x) { return fmaf(0.5f, tanha(0.5f * x), 0.5f); }
__device__ __forceinline__ u32 t32(float v) {
    u32 r; asm("cvt.rna.tf32.f32 %0, %1;" : "=r"(r) : "f"(v)); return r;
}

// d = a(16x8 tf32) @ b(8x8 tf32) + c
__device__ __forceinline__ void mma8(float d[4], const u32 a[4], const u32 b[2],
                                     const float c[4]) {
    asm("mma.sync.aligned.m16n8k8.row.col.f32.tf32.tf32.f32 "
        "{%0,%1,%2,%3}, {%4,%5,%6,%7}, {%8,%9}, {%10,%11,%12,%13};"
        : "=f"(d[0]), "=f"(d[1]), "=f"(d[2]), "=f"(d[3])
        : "r"(a[0]), "r"(a[1]), "r"(a[2]), "r"(a[3]),
          "r"(b[0]), "r"(b[1]),
          "f"(c[0]), "f"(c[1]), "f"(c[2]), "f"(c[3]));
}

// Accumulator position p holds h component pi(p): lane accum slots == next-step
// A-frag slots, so the recurrence needs no shuffles.
__device__ __forceinline__ int pi_map(int p) {
    return (p < 8) ? ((p >> 1) | ((p & 1) << 2))
                   : (8 | (((p - 8) >> 1)) | ((p & 1) << 2));
}

// B (h-part only) element: col = permuted output col (0..47), k = 0..15
// groups: col/16 = 0:r  1:z  2:h_n     (all read w_hh)
__device__ __forceinline__ float bval_h(const float* w_hh, int col, int k) {
    int grp = col >> 4;
    int g = pi_map(col & 15) + grp * 16;
    return w_hh[g * 16 + k];
}

__global__ void __launch_bounds__(192, 2)
gru_adder_kernel(const float* __restrict__ x,
                 const float* __restrict__ w_ih,   // [48,2]
                 const float* __restrict__ w_hh,   // [48,16]
                 const float* __restrict__ b_ih,   // [48]
                 const float* __restrict__ b_hh,   // [48]
                 const float* __restrict__ w_sum,  // [16]
                 const float* __restrict__ b_sum,  // [1]
                 const float* __restrict__ w_car,  // [16]
                 const float* __restrict__ b_car,  // [1]
                 float* __restrict__ out_hidden,   // [B,4,16]
                 float* __restrict__ out_sums,     // [B,4]
                 float* __restrict__ out_carry,    // [B]
                 float* __restrict__ out_ol,       // [B,5]
                 int Bn)
{
    const int warp = threadIdx.x >> 5;
    const int l = threadIdx.x & 31;
    const int q = l & 3;      // lane quad position
    const int a = l >> 2;     // row group: rows a and a+8

    // ---------- per-lane B fragments (hi/lo tf32 split), h-chunks only ----------
    // tiles 0,1: r ; tiles 2,3: z
    u32 Bh[4][2][2], Bl[4][2][2];
#pragma unroll
    for (int nt = 0; nt < 4; nt++) {
#pragma unroll
        for (int kc = 0; kc < 2; kc++) {
            int col = nt * 8 + a;
            float v0 = bval_h(w_hh, col, kc * 8 + q);
            float v1 = bval_h(w_hh, col, kc * 8 + q + 4);
            Bh[nt][kc][0] = t32(v0);
            Bl[nt][kc][0] = t32(v0 - __uint_as_float(Bh[nt][kc][0]));
            Bh[nt][kc][1] = t32(v1);
            Bl[nt][kc][1] = t32(v1 - __uint_as_float(Bh[nt][kc][1]));
        }
    }
    // h_n tiles 4,5
    u32 Hh[2][2][2], Hl[2][2][2];
#pragma unroll
    for (int ti = 0; ti < 2; ti++) {
#pragma unroll
        for (int kc = 0; kc < 2; kc++) {
            int col = 32 + ti * 8 + a;
            float v0 = bval_h(w_hh, col, kc * 8 + q);
            float v1 = bval_h(w_hh, col, kc * 8 + q + 4);
            Hh[ti][kc][0] = t32(v0);
            Hl[ti][kc][0] = t32(v0 - __uint_as_float(Hh[ti][kc][0]));
            Hh[ti][kc][1] = t32(v1);
            Hl[ti][kc][1] = t32(v1 - __uint_as_float(Hh[ti][kc][1]));
        }
    }

    // ---------- per-lane x weights (scalar path, exact fp32) ----------
    // wx[0..3]: rz tiles 0..3 ; wx[4,5]: i_n tiles 6,7. Index [pr] = col 2q+pr.
    float wx0[6][2], wx1[6][2];
#pragma unroll
    for (int nt = 0; nt < 4; nt++) {
#pragma unroll
        for (int pr = 0; pr < 2; pr++) {
            int col = nt * 8 + 2 * q + pr;
            int g = pi_map(col & 15) + (col >> 4) * 16;
            wx0[nt][pr] = w_ih[g * 2];
            wx1[nt][pr] = w_ih[g * 2 + 1];
        }
    }
#pragma unroll
    for (int ti = 0; ti < 2; ti++) {
#pragma unroll
        for (int pr = 0; pr < 2; pr++) {
            int col = (6 + ti) * 8 + 2 * q + pr;
            int g = pi_map(col & 15) + 32;
            wx0[4 + ti][pr] = w_ih[g * 2];
            wx1[4 + ti][pr] = w_ih[g * 2 + 1];
        }
    }

    // ---------- per-lane bias init ----------
    // cb[0..3]: rz (b_ih+b_hh) ; cb[4,5]: h_n (b_hh) ; cb[6,7]: i_n (b_ih)
    float cb[8][2];
#pragma unroll
    for (int nt = 0; nt < 8; nt++) {
#pragma unroll
        for (int pr = 0; pr < 2; pr++) {
            int col = nt * 8 + 2 * q + pr;
            int grp = col >> 4;
            int g = pi_map(col & 15);
            float v;
            if (grp == 0)      v = b_ih[g] + b_hh[g];
            else if (grp == 1) v = b_ih[16 + g] + b_hh[16 + g];
            else if (grp == 2) v = b_hh[32 + g];
            else               v = b_ih[32 + g];
            cb[nt][pr] = v;
        }
    }

    // sum / carry weights at this lane's h components {q, q+4, 8+q, 12+q}
    float ws[4], wc[4];
#pragma unroll
    for (int m = 0; m < 4; m++) {
        int j = q + ((m & 1) << 2) + ((m >> 1) << 3);
        ws[m] = w_sum[j];
        wc[m] = w_car[j];
    }
    const float bs = b_sum[0];
    const float bc = b_car[0];

    // ---------- persistent loop over 16-row tiles ----------
    const int ntiles = Bn >> 4;
    const int nwarp = blockDim.x >> 5;

    for (int tile = blockIdx.x * nwarp + warp; tile < ntiles;
         tile += gridDim.x * nwarp) {
        const int e0 = tile * 16;
        const int er0 = e0 + a, er1 = e0 + a + 8;

        // this lane's two rows of x (8 floats each)
        const float4* xv0 = reinterpret_cast<const float4*>(x + (size_t)er0 * 8);
        const float4* xv1 = reinterpret_cast<const float4*>(x + (size_t)er1 * 8);
        float4 A0 = xv0[0], A1 = xv0[1], C0 = xv1[0], C1 = xv1[1];
        float xs0[8] = {A0.x, A0.y, A0.z, A0.w, A1.x, A1.y, A1.z, A1.w};
        float xs1[8] = {C0.x, C0.y, C0.z, C0.w, C1.x, C1.y, C1.z, C1.w};

        // h state: hr0[m]/hr1[m] = h[row][component q+4*(m&1)+8*(m>>1)]
        float hr0[4] = {0.f, 0.f, 0.f, 0.f};
        float hr1[4] = {0.f, 0.f, 0.f, 0.f};

        float* oh0 = out_hidden + (size_t)er0 * 64;
        float* oh1 = out_hidden + (size_t)er1 * 64;

#pragma unroll
        for (int t = 0; t < 4; t++) {
            const float x00 = xs0[2 * t], x01 = xs0[2 * t + 1];
            const float x10 = xs1[2 * t], x11 = xs1[2 * t + 1];

            // acc init: biases + exact scalar x contribution
            float acc[6][4];
#pragma unroll
            for (int nt = 0; nt < 4; nt++) {
#pragma unroll
                for (int pr = 0; pr < 2; pr++) {
                    acc[nt][pr]     = fmaf(x01, wx1[nt][pr], fmaf(x00, wx0[nt][pr], cb[nt][pr]));
                    acc[nt][2 + pr] = fmaf(x11, wx1[nt][pr], fmaf(x10, wx0[nt][pr], cb[nt][pr]));
                }
            }
#pragma unroll
            for (int ti = 0; ti < 2; ti++) {
#pragma unroll
                for (int pr = 0; pr < 2; pr++) {
                    acc[4 + ti][pr]     = cb[4 + ti][pr];
                    acc[4 + ti][2 + pr] = cb[4 + ti][pr];
                }
            }
            // i_n (pure scalar, no h dependency)
            float in0[4], in1[4];
#pragma unroll
            for (int ti = 0; ti < 2; ti++) {
#pragma unroll
                for (int pr = 0; pr < 2; pr++) {
                    in0[ti * 2 + pr] = fmaf(x01, wx1[4 + ti][pr], fmaf(x00, wx0[4 + ti][pr], cb[6 + ti][pr]));
                    in1[ti * 2 + pr] = fmaf(x11, wx1[4 + ti][pr], fmaf(x10, wx0[4 + ti][pr], cb[6 + ti][pr]));
                }
            }

            if (t > 0) {
                // A-frags straight from accum-layout h, single tf32 (weights
                // carry the hi/lo split; h quantization error ~2^-11 rel)
                u32 ahh[2][4];
#pragma unroll
                for (int kc = 0; kc < 2; kc++) {
                    ahh[kc][0] = t32(hr0[2 * kc]);
                    ahh[kc][1] = t32(hr1[2 * kc]);
                    ahh[kc][2] = t32(hr0[2 * kc + 1]);
                    ahh[kc][3] = t32(hr1[2 * kc + 1]);
                }
#pragma unroll
                for (int nt = 0; nt < 4; nt++) {
#pragma unroll
                    for (int kc = 0; kc < 2; kc++) {
                        mma8(acc[nt], ahh[kc], Bh[nt][kc], acc[nt]);
                        mma8(acc[nt], ahh[kc], Bl[nt][kc], acc[nt]);
                    }
                }
#pragma unroll
                for (int ti = 0; ti < 2; ti++) {
#pragma unroll
                    for (int kc = 0; kc < 2; kc++) {
                        mma8(acc[4 + ti], ahh[kc], Hh[ti][kc], acc[4 + ti]);
                        mma8(acc[4 + ti], ahh[kc], Hl[ti][kc], acc[4 + ti]);
                    }
                }
            }

            // ---------- epilogue: activations + h update ----------
#pragma unroll
            for (int m = 0; m < 4; m++) {
                const int toff = m >> 1, pr = m & 1;
                {
                    float r = sigm(acc[toff][pr]);
                    float z = sigm(acc[2 + toff][pr]);
                    float n = tanha(fmaf(r, acc[4 + toff][pr], in0[toff * 2 + pr]));
                    hr0[m] = fmaf(z, hr0[m] - n, n);
                }
                {
                    float r = sigm(acc[toff][2 + pr]);
                    float z = sigm(acc[2 + toff][2 + pr]);
                    float n = tanha(fmaf(r, acc[4 + toff][2 + pr], in1[toff * 2 + pr]));
                    hr1[m] = fmaf(z, hr1[m] - n, n);
                }
                const int col = q + ((m & 1) << 2) + ((m >> 1) << 3);
                oh0[t * 16 + col] = hr0[m];
                oh1[t * 16 + col] = hr1[m];
            }

            // ---------- sum logits ----------
            float s0 = hr0[0] * ws[0] + hr0[1] * ws[1] + hr0[2] * ws[2] + hr0[3] * ws[3];
            float s1 = hr1[0] * ws[0] + hr1[1] * ws[1] + hr1[2] * ws[2] + hr1[3] * ws[3];
            s0 += __shfl_xor_sync(FULL, s0, 1);
            s0 += __shfl_xor_sync(FULL, s0, 2);
            s1 += __shfl_xor_sync(FULL, s1, 1);
            s1 += __shfl_xor_sync(FULL, s1, 2);
            if (q == 0) {
                out_sums[(size_t)er0 * 4 + t] = s0 + bs;
                out_sums[(size_t)er1 * 4 + t] = s1 + bs;
                out_ol[(size_t)er0 * 5 + t] = s0 + bs;
                out_ol[(size_t)er1 * 5 + t] = s1 + bs;
            }
        }

        // ---------- carry logit ----------
        float c0 = hr0[0] * wc[0] + hr0[1] * wc[1] + hr0[2] * wc[2] + hr0[3] * wc[3];
        float c1 = hr1[0] * wc[0] + hr1[1] * wc[1] + hr1[2] * wc[2] + hr1[3] * wc[3];
        c0 += __shfl_xor_sync(FULL, c0, 1);
        c0 += __shfl_xor_sync(FULL, c0, 2);
        c1 += __shfl_xor_sync(FULL, c1, 1);
        c1 += __shfl_xor_sync(FULL, c1, 2);
        if (q == 0) {
            out_carry[er0] = c0 + bc;
            out_carry[er1] = c1 + bc;
            out_ol[(size_t)er0 * 5 + 4] = c0 + bc;
            out_ol[(size_t)er1 * 5 + 4] = c1 + bc;
        }
    }
}

// ---------------- launch ----------------

extern "C" void kernel_launch(void* const* d_in, const int* in_sizes, int n_in,
                              void* d_out, int out_size)
{
    const float* x     = (const float*)d_in[0];
    const float* w_ih  = (const float*)d_in[1];
    const float* w_hh  = (const float*)d_in[2];
    const float* b_ih  = (const float*)d_in[3];
    const float* b_hh  = (const float*)d_in[4];
    const float* w_sum = (const float*)d_in[5];
    const float* b_sum = (const float*)d_in[6];
    const float* w_car = (const float*)d_in[7];
    const float* b_car = (const float*)d_in[8];

    const int B = in_sizes[0] / 8;   // x is [B, 4, 2]

    float* out = (float*)d_out;
    float* out_hidden = out;                              // B*64
    float* out_sums   = out_hidden + (size_t)B * 64;      // B*4
    float* out_carry  = out_sums + (size_t)B * 4;         // B
    float* out_ol     = out_carry + (size_t)B;            // B*5

    const int threads = 192;                // 6 warps/block, 2 blocks/SM
    int blocks = 296;
    int maxb = (B / 16 + 5) / 6;
    if (blocks > maxb) blocks = maxb;
    if (blocks < 1) blocks = 1;

    gru_adder_kernel<<<blocks, threads>>>(x, w_ih, w_hh, b_ih, b_hh,
                                          w_sum, b_sum, w_car, b_car,
                                          out_hidden, out_sums, out_carry,
                                          out_ol, B);
}